// round 15
// baseline (speedup 1.0000x reference)
#include <cuda_runtime.h>
#include <cstdint>

// Problem constants
#define NROWS   131072
#define VDIM    128
#define KCODES  512
#define TNF     0.678822509939086f   // fl32(0.06 * sqrt(128))

#define TIE_EPS 4e-7                 // fp64 near-tie margin (R7-R9 passing rule)
#define GAP_THR 1e-4f                // fp32 gap below which fp64 refine runs
#define BAND    2.5e-3f              // tf32 candidate band >= GAP_THR + 4*tf32 dot err
#define FLAGCAP 32

#define O1_OFF  (131072*128)
#define O2_OFF  (O1_OFF + 131072)
#define OE_OFF  (O2_OFF + 131072)

// ---------------- scratch ------------------------------------------------------
__device__ float  g_emb[KCODES*VDIM];     // normalized codebook fp32, code-major
__device__ float  g_embF[KCODES*VDIM];    // tf32 codebook in MMA fragment order:
                                          // [code][t(4)][m(32)], k = t + 4m
__device__ float  g_e2[KCODES];
__device__ double g_e2d[KCODES];
__device__ int    g_hist[KCODES];         // zero at start; re-zeroed by last block
__device__ int    g_done;                 // zero at start; re-zeroed by last block

// ---------------- helpers ------------------------------------------------------
__device__ __forceinline__ float wredsum(float v) {
    #pragma unroll
    for (int o = 16; o > 0; o >>= 1) v += __shfl_xor_sync(0xffffffffu, v, o);
    return v;
}
__device__ __forceinline__ double wredsumd(double v) {
    #pragma unroll
    for (int o = 16; o > 0; o >>= 1) v += __shfl_xor_sync(0xffffffffu, v, o);
    return v;
}
__device__ __forceinline__ uint32_t tf32b(float x) {
    unsigned r;
    asm("cvt.rna.tf32.f32 %0, %1;" : "=r"(r) : "f"(x));
    return r;
}
__device__ __forceinline__ void mma_tf32(float& d0, float& d1, float& d2, float& d3,
                                         uint32_t a0, uint32_t a1, uint32_t a2, uint32_t a3,
                                         uint32_t b0, uint32_t b1) {
    asm volatile("mma.sync.aligned.m16n8k8.row.col.f32.tf32.tf32.f32 "
                 "{%0,%1,%2,%3}, {%4,%5,%6,%7}, {%8,%9}, {%0,%1,%2,%3};"
                 : "+f"(d0), "+f"(d1), "+f"(d2), "+f"(d3)
                 : "r"(a0), "r"(a1), "r"(a2), "r"(a3), "r"(b0), "r"(b1));
}
__device__ __forceinline__ void t2ins(float& b1, int& i1, float& b2, int& i2, float s, int c) {
    if (s < b1 || (s == b1 && c < i1)) { b2 = b1; i2 = i1; b1 = s; i1 = c; }
    else if (s < b2 || (s == b2 && c < i2)) { b2 = s; i2 = c; }
}
__device__ __forceinline__ void ins4(float* ts, int* tc, float s, int c) {
    if (s < ts[3]) {
        if (s < ts[1]) {
            ts[3] = ts[2]; tc[3] = tc[2]; ts[2] = ts[1]; tc[2] = tc[1];
            if (s < ts[0]) { ts[1] = ts[0]; tc[1] = tc[0]; ts[0] = s; tc[0] = c; }
            else           { ts[1] = s; tc[1] = c; }
        } else {
            if (s < ts[2]) { ts[3] = ts[2]; tc[3] = tc[2]; ts[2] = s; tc[2] = c; }
            else           { ts[3] = s; tc[3] = c; }
        }
    }
}

// ---------------- kernel 0: normalize codebook + fragment pack ------------------
// 64 blocks x 256 threads; one warp per code. (chains identical to R7-R14)
__global__ void k0_emb(const float* __restrict__ emb0) {
    const int tid = threadIdx.x, w = tid >> 5, tx = tid & 31;
    const int c = blockIdx.x * 8 + w;

    float4 v = *reinterpret_cast<const float4*>(&emb0[c * VDIM + tx * 4]);
    float p0 = __fmul_rn(v.x, v.x), p1 = __fmul_rn(v.y, v.y);
    float p2 = __fmul_rn(v.z, v.z), p3 = __fmul_rn(v.w, v.w);
    float ss = wredsum(__fadd_rn(__fadd_rn(__fadd_rn(p0, p1), p2), p3));
    float nrm = __fsqrt_rn(ss);

    float4 e;
    e.x = __fdiv_rn(__fmul_rn(TNF, v.x), nrm);
    e.y = __fdiv_rn(__fmul_rn(TNF, v.y), nrm);
    e.z = __fdiv_rn(__fmul_rn(TNF, v.z), nrm);
    e.w = __fdiv_rn(__fmul_rn(TNF, v.w), nrm);

    *reinterpret_cast<float4*>(&g_emb[c * VDIM + tx * 4]) = e;

    // fragment pack: k = 4*tx + j ; dst = c*128 + (k&3)*32 + 2*(k>>3) + ((k>>2)&1)
    float ev[4] = {e.x, e.y, e.z, e.w};
    #pragma unroll
    for (int j = 0; j < 4; ++j) {
        int k = tx * 4 + j;
        int dst = c * VDIM + (k & 3) * 32 + 2 * (k >> 3) + ((k >> 2) & 1);
        g_embF[dst] = __uint_as_float(tf32b(ev[j]));
    }

    double e2d = (double)e.x*e.x + (double)e.y*e.y + (double)e.z*e.z + (double)e.w*e.w;
    e2d = wredsumd(e2d);
    if (tx == 0) { g_e2d[c] = e2d; g_e2[c] = (float)e2d; }
}

// ---------------- kernel 2: tf32 mma filter (direct-L2 B) + rescore + outputs ---
#define MT        128
#define XS_STRIDE 132
#define SM_XS     0                                   // 67584
#define SM_E2     67584                               // 2048  -> 69632
#define SM_S2     69632                               // 512   -> 70144
#define SM_IDX    70144                               // 512   -> 70656
#define SM_RC     70656                               // 512   -> 71168
#define SM_FLAG   71168                               // 392   -> 71568 (pad)
#define SM_WLC    71568                               // 16    -> 71584
#define SM_CAND   71584                               // 8192  -> 79776
#define SM_CSC    79776                               // 8192  -> 87968
#define SM_WL     87968                               // 8192  -> 96160
#define SM_TOTAL  96256

__global__ void __launch_bounds__(256, 2)
k2_fused(const float* __restrict__ x0, float* __restrict__ out) {
    extern __shared__ char smem[];
    float* xs    = reinterpret_cast<float*>(smem + SM_XS);
    float* e2s   = reinterpret_cast<float*>(smem + SM_E2);
    float* s_s2  = reinterpret_cast<float*>(smem + SM_S2);
    int*   s_idx = reinterpret_cast<int*>(smem + SM_IDX);
    int*   s_rc  = reinterpret_cast<int*>(smem + SM_RC);
    int*   s_flag= reinterpret_cast<int*>(smem + SM_FLAG);
    int*   s_wlc = reinterpret_cast<int*>(smem + SM_WLC);
    int*   s_cand= reinterpret_cast<int*>(smem + SM_CAND);
    float* s_csc = reinterpret_cast<float*>(smem + SM_CSC);
    int*   s_wl  = reinterpret_cast<int*>(smem + SM_WL);

    const int tid = threadIdx.x, w = tid >> 5, tx = tid & 31;
    const int g = tx >> 2, t = tx & 3;
    const int rb = blockIdx.x * MT;
    const float FMAX = 3.402823466e38f;

    // ---- x tile: normalize (bit-identical chain), s2 ----
    #pragma unroll
    for (int it = 0; it < 16; ++it) {
        int r = it * 8 + w;
        float4 xv = *reinterpret_cast<const float4*>(&x0[(size_t)(rb + r) * VDIM + tx * 4]);
        float p0 = __fmul_rn(xv.x, xv.x), p1 = __fmul_rn(xv.y, xv.y);
        float p2 = __fmul_rn(xv.z, xv.z), p3 = __fmul_rn(xv.w, xv.w);
        float ss = wredsum(__fadd_rn(__fadd_rn(__fadd_rn(p0, p1), p2), p3));
        float nrm = __fsqrt_rn(ss);
        float4 o;
        o.x = __fdiv_rn(__fmul_rn(TNF, xv.x), nrm);
        o.y = __fdiv_rn(__fmul_rn(TNF, xv.y), nrm);
        o.z = __fdiv_rn(__fmul_rn(TNF, xv.z), nrm);
        o.w = __fdiv_rn(__fmul_rn(TNF, xv.w), nrm);
        *reinterpret_cast<float4*>(&xs[r * XS_STRIDE + tx * 4]) = o;
        float ea = o.x - xv.x, eb = o.y - xv.y, ec = o.z - xv.z, ed = o.w - xv.w;
        float s2 = wredsum(ea*ea + eb*eb + ec*ec + ed*ed);
        if (tx == 0) s_s2[r] = s2;
    }
    e2s[tid] = g_e2[tid];
    e2s[tid + 256] = g_e2[tid + 256];
    if (tid < MT) s_rc[tid] = 0;
    if (tid == 0) { s_flag[0] = 0; s_wlc[0] = 0; }
    __syncthreads();

    // ---- A fragments: warp w owns rows w*16 .. w*16+15; tf32 in regs ----
    uint32_t afr[16][4];
    {
        const float* xw = xs + (w * 16) * XS_STRIDE;
        #pragma unroll
        for (int ks = 0; ks < 16; ++ks) {
            afr[ks][0] = tf32b(xw[ g      * XS_STRIDE + ks * 8 + t    ]);
            afr[ks][1] = tf32b(xw[(g + 8) * XS_STRIDE + ks * 8 + t    ]);
            afr[ks][2] = tf32b(xw[ g      * XS_STRIDE + ks * 8 + t + 4]);
            afr[ks][3] = tf32b(xw[(g + 8) * XS_STRIDE + ks * 8 + t + 4]);
        }
    }

    float tsA[4] = {FMAX, FMAX, FMAX, FMAX}, tsB[4] = {FMAX, FMAX, FMAX, FMAX};
    int   tcA[4] = {0, 0, 0, 0},             tcB[4] = {0, 0, 0, 0};

    // ---- mainloop: B fragments straight from L2 (no staging, no syncs) ----
    for (int ct = 0; ct < 64; ++ct) {
        float d0 = 0.f, d1 = 0.f, d2 = 0.f, d3 = 0.f;
        const int codeB = ct * 8 + g;     // code this lane supplies B for
        const float4* bp4 = reinterpret_cast<const float4*>(
            &g_embF[codeB * VDIM + t * 32]);
        #pragma unroll
        for (int ks2 = 0; ks2 < 8; ++ks2) {
            float4 bq = __ldg(bp4 + ks2);
            int ks = ks2 * 2;
            mma_tf32(d0, d1, d2, d3,
                     afr[ks][0], afr[ks][1], afr[ks][2], afr[ks][3],
                     __float_as_uint(bq.x), __float_as_uint(bq.y));
            mma_tf32(d0, d1, d2, d3,
                     afr[ks+1][0], afr[ks+1][1], afr[ks+1][2], afr[ks+1][3],
                     __float_as_uint(bq.z), __float_as_uint(bq.w));
        }
        int c0 = ct * 8 + t * 2;          // codes this lane's accumulators hold
        float2 e2v = *reinterpret_cast<const float2*>(&e2s[c0]);
        float sA0 = __fsub_rn(e2v.x, __fmul_rn(2.0f, d0));
        float sA1 = __fsub_rn(e2v.y, __fmul_rn(2.0f, d1));
        float sB0 = __fsub_rn(e2v.x, __fmul_rn(2.0f, d2));
        float sB1 = __fsub_rn(e2v.y, __fmul_rn(2.0f, d3));
        ins4(tsA, tcA, sA0, c0); ins4(tsA, tcA, sA1, c0 + 1);
        ins4(tsB, tcB, sB0, c0); ins4(tsB, tcB, sB1, c0 + 1);
    }

    // ---- per-row candidate collection (group-of-4 lanes per row) ----
    {
        #pragma unroll
        for (int h = 0; h < 2; ++h) {
            float* ts = h ? tsB : tsA;
            int*   tc = h ? tcB : tcA;
            int row = w * 16 + g + h * 8;
            float gb = ts[0];
            gb = fminf(gb, __shfl_xor_sync(0xffffffffu, gb, 1));
            gb = fminf(gb, __shfl_xor_sync(0xffffffffu, gb, 2));
            float th = __fadd_rn(gb, BAND);
            int ov = (ts[3] <= th) ? 1 : 0;
            ov |= __shfl_xor_sync(0xffffffffu, ov, 1);
            ov |= __shfl_xor_sync(0xffffffffu, ov, 2);
            if (ov) {
                if (t == 0) s_rc[row] = -1;          // fallback sentinel
            } else {
                #pragma unroll
                for (int i = 0; i < 4; ++i) {
                    if (ts[i] <= th) {
                        int pos = atomicAdd(&s_rc[row], 1);
                        s_cand[row * 16 + pos] = tc[i];
                    }
                }
            }
        }
    }
    __syncthreads();

    // ---- worklist ----
    if (tid < MT) {
        int rc = s_rc[tid];
        for (int s = 0; s < rc; ++s) {
            int pos = atomicAdd(s_wlc, 1);
            s_wl[pos] = tid * 16 + s;
        }
    }
    __syncthreads();

    // ---- exact fp32-chain rescore (bitwise identical chain to R7-R14) ----
    int wlc = s_wlc[0];
    for (int p = tid; p < wlc; p += 256) {
        int ent = s_wl[p];
        int r = ent >> 4, slot = ent & 15;
        int code = s_cand[ent];
        const float* xr = xs + r * XS_STRIDE;
        const float* er = g_emb + code * VDIM;
        float acc = 0.0f;
        #pragma unroll 8
        for (int k4 = 0; k4 < 32; ++k4) {
            float4 xv = *reinterpret_cast<const float4*>(xr + k4 * 4);
            float4 ev = *reinterpret_cast<const float4*>(er + k4 * 4);
            acc = __fmaf_rn(xv.x, ev.x, acc);
            acc = __fmaf_rn(xv.y, ev.y, acc);
            acc = __fmaf_rn(xv.z, ev.z, acc);
            acc = __fmaf_rn(xv.w, ev.w, acc);
        }
        s_csc[r * 16 + slot] = __fsub_rn(e2s[code], __fmul_rn(2.0f, acc));
    }
    __syncthreads();

    // ---- per-row top-2 over exact scores + gap flag ----
    if (tid < MT && s_rc[tid] > 0) {
        int rc = s_rc[tid];
        float b1 = FMAX, b2 = FMAX;
        int i1 = 0x3fffffff, i2 = 0x3fffffff;
        for (int s = 0; s < rc; ++s)
            t2ins(b1, i1, b2, i2, s_csc[tid * 16 + s], s_cand[tid * 16 + s]);
        s_idx[tid] = i1;
        if (__fsub_rn(b2, b1) < GAP_THR) {
            int e = atomicAdd(&s_flag[0], 1);
            if (e < FLAGCAP) {
                s_flag[1 + 3*e + 0] = tid;
                s_flag[1 + 3*e + 1] = i1;
                s_flag[1 + 3*e + 2] = i2;
            }
        }
    }
    __syncthreads();

    // ---- fallback rows: exact full-scan, warp per row ----
    for (int r = w; r < MT; r += 8) {
        if (s_rc[r] >= 0) continue;
        const float* xr = xs + r * XS_STRIDE;
        float b1 = FMAX, b2 = FMAX;
        int i1 = 0x3fffffff, i2 = 0x3fffffff;
        for (int j = 0; j < 16; ++j) {
            int code = j * 32 + tx;
            const float* er = g_emb + code * VDIM;
            float acc = 0.0f;
            #pragma unroll 8
            for (int k4 = 0; k4 < 32; ++k4) {
                float4 xv = *reinterpret_cast<const float4*>(xr + k4 * 4);
                float4 ev = *reinterpret_cast<const float4*>(er + k4 * 4);
                acc = __fmaf_rn(xv.x, ev.x, acc);
                acc = __fmaf_rn(xv.y, ev.y, acc);
                acc = __fmaf_rn(xv.z, ev.z, acc);
                acc = __fmaf_rn(xv.w, ev.w, acc);
            }
            t2ins(b1, i1, b2, i2, __fsub_rn(e2s[code], __fmul_rn(2.0f, acc)), code);
        }
        #pragma unroll
        for (int off = 16; off > 0; off >>= 1) {
            float ob1 = __shfl_xor_sync(0xffffffffu, b1, off);
            int   oi1 = __shfl_xor_sync(0xffffffffu, i1, off);
            float ob2 = __shfl_xor_sync(0xffffffffu, b2, off);
            int   oi2 = __shfl_xor_sync(0xffffffffu, i2, off);
            t2ins(b1, i1, b2, i2, ob1, oi1);
            t2ins(b1, i1, b2, i2, ob2, oi2);
        }
        if (tx == 0) {
            s_idx[r] = i1;
            if (__fsub_rn(b2, b1) < GAP_THR) {
                int e = atomicAdd(&s_flag[0], 1);
                if (e < FLAGCAP) {
                    s_flag[1 + 3*e + 0] = r;
                    s_flag[1 + 3*e + 1] = i1;
                    s_flag[1 + 3*e + 2] = i2;
                }
            }
        }
    }
    __syncthreads();

    // ---- fp64 margin refine (warp 0; bit-identical to R7-R14 path) ----
    if (w == 0) {
        int cnt = s_flag[0]; if (cnt > FLAGCAP) cnt = FLAGCAP;
        for (int e = 0; e < cnt; ++e) {
            int r  = s_flag[1 + 3*e + 0];
            int i1 = s_flag[1 + 3*e + 1];
            int i2 = s_flag[1 + 3*e + 2];
            float4 xn = *reinterpret_cast<const float4*>(&xs[r * XS_STRIDE + tx * 4]);
            float4 e1 = *reinterpret_cast<const float4*>(&g_emb[i1 * VDIM + tx * 4]);
            float4 e2 = *reinterpret_cast<const float4*>(&g_emb[i2 * VDIM + tx * 4]);
            double d1 = (double)xn.x*e1.x + (double)xn.y*e1.y + (double)xn.z*e1.z + (double)xn.w*e1.w;
            double d2 = (double)xn.x*e2.x + (double)xn.y*e2.y + (double)xn.z*e2.z + (double)xn.w*e2.w;
            d1 = wredsumd(d1); d2 = wredsumd(d2);
            double s1d = g_e2d[i1] - 2.0 * d1;
            double s2d = g_e2d[i2] - 2.0 * d2;
            bool w2 = (s2d < s1d) || (s2d == s1d && i2 < i1);
            double margin = w2 ? (s1d - s2d) : (s2d - s1d);
            bool take2 = w2 ^ (margin < TIE_EPS);
            if (tx == 0 && take2) s_idx[r] = i2;
        }
    }
    __syncthreads();

    // ---- outputs ----
    #pragma unroll
    for (int it = 0; it < 16; ++it) {
        int r   = it * 8 + w;
        int idx = s_idx[r];
        float4 xn = *reinterpret_cast<const float4*>(&xs[r * XS_STRIDE + tx * 4]);
        float4 ev = *reinterpret_cast<const float4*>(&g_emb[idx * VDIM + tx * 4]);
        float4 o0;
        o0.x = __fadd_rn(__fsub_rn(ev.x, xn.x), xn.x);
        o0.y = __fadd_rn(__fsub_rn(ev.y, xn.y), xn.y);
        o0.z = __fadd_rn(__fsub_rn(ev.z, xn.z), xn.z);
        o0.w = __fadd_rn(__fsub_rn(ev.w, xn.w), xn.w);
        *reinterpret_cast<float4*>(&out[(size_t)(rb + r) * VDIM + tx * 4]) = o0;

        float da = xn.x - ev.x, db = xn.y - ev.y, dc = xn.z - ev.z, dd = xn.w - ev.w;
        float s1 = wredsum(da*da + db*db + dc*dc + dd*dd);
        if (tx == 0) {
            out[O1_OFF + rb + r] = s1;
            out[O2_OFF + rb + r] = __fadd_rn(s1, s_s2[r]);
            atomicAdd(&g_hist[idx], 1);
        }
    }

    // ---- last block: entropy + hist/counter reset (replaces k4/k5) ----
    __syncthreads();
    if (tid == 0) {
        __threadfence();
        int v = atomicAdd(&g_done, 1);
        s_wlc[1] = (v == (int)gridDim.x - 1) ? 1 : 0;
    }
    __syncthreads();
    if (s_wlc[1]) {
        __threadfence();
        int h0 = g_hist[tid], h1 = g_hist[tid + 256];
        float pa = (float)h0 * (1.0f / 131072.0f);
        float pb = (float)h1 * (1.0f / 131072.0f);
        float term = ((h0 > 0) ? (-pa * logf(pa)) : 0.0f)
                   + ((h1 > 0) ? (-pb * logf(pb)) : 0.0f);
        term = wredsum(term);
        __shared__ float ws[8];
        if (tx == 0) ws[w] = term;
        __syncthreads();
        if (tid < 32) {
            float vsum = (tid < 8) ? ws[tid] : 0.0f;
            #pragma unroll
            for (int o = 4; o > 0; o >>= 1) vsum += __shfl_xor_sync(0xffffffffu, vsum, o);
            if (tid == 0) { out[OE_OFF] = vsum; g_done = 0; }
        }
        g_hist[tid] = 0; g_hist[tid + 256] = 0;
    }
}

// ---------------- launch --------------------------------------------------------
extern "C" void kernel_launch(void* const* d_in, const int* in_sizes, int n_in,
                              void* d_out, int out_size) {
    const float* x0   = (const float*)d_in[0];
    const float* emb0 = (const float*)d_in[1];
    if (n_in >= 2 && in_sizes[0] == KCODES * VDIM) {
        x0   = (const float*)d_in[1];
        emb0 = (const float*)d_in[0];
    }
    float* out = (float*)d_out;

    cudaFuncSetAttribute(k2_fused,
                         cudaFuncAttributeMaxDynamicSharedMemorySize, SM_TOTAL);

    k0_emb<<<64, 256>>>(emb0);
    k2_fused<<<NROWS / MT, 256, SM_TOTAL>>>(x0, out);
}

// round 16
// speedup vs baseline: 2.3318x; 2.3318x over previous
#include <cuda_runtime.h>
#include <cstdint>

// Problem constants
#define NROWS   131072
#define VDIM    128
#define KCODES  512
#define TNF     0.678822509939086f   // fl32(0.06 * sqrt(128))

#define TIE_EPS 4e-7                 // fp64 near-tie margin (R7-R9 passing rule)
#define GAP_THR 1e-4f                // fp32 gap below which fp64 refine runs
#define BAND    2.5e-3f              // tf32 candidate band >= GAP_THR + 4*tf32 dot err
#define FLAGCAP 32

#define O1_OFF  (131072*128)
#define O2_OFF  (O1_OFF + 131072)
#define OE_OFF  (O2_OFF + 131072)

// ---------------- scratch ------------------------------------------------------
__device__ float  g_emb[KCODES*VDIM];     // normalized codebook fp32, code-major
__device__ float  g_embF[KCODES*VDIM];    // tf32 codebook in MMA fragment order
__device__ float  g_e2[KCODES];
__device__ double g_e2d[KCODES];
__device__ int    g_hist[KCODES];         // zero at start; re-zeroed by last block
__device__ int    g_done;                 // zero at start; re-zeroed by last block

// ---------------- helpers ------------------------------------------------------
__device__ __forceinline__ float wredsum(float v) {
    #pragma unroll
    for (int o = 16; o > 0; o >>= 1) v += __shfl_xor_sync(0xffffffffu, v, o);
    return v;
}
__device__ __forceinline__ double wredsumd(double v) {
    #pragma unroll
    for (int o = 16; o > 0; o >>= 1) v += __shfl_xor_sync(0xffffffffu, v, o);
    return v;
}
__device__ __forceinline__ uint32_t tf32b(float x) {
    unsigned r;
    asm("cvt.rna.tf32.f32 %0, %1;" : "=r"(r) : "f"(x));
    return r;
}
__device__ __forceinline__ void mma_tf32(float& d0, float& d1, float& d2, float& d3,
                                         uint32_t a0, uint32_t a1, uint32_t a2, uint32_t a3,
                                         uint32_t b0, uint32_t b1) {
    asm volatile("mma.sync.aligned.m16n8k8.row.col.f32.tf32.tf32.f32 "
                 "{%0,%1,%2,%3}, {%4,%5,%6,%7}, {%8,%9}, {%0,%1,%2,%3};"
                 : "+f"(d0), "+f"(d1), "+f"(d2), "+f"(d3)
                 : "r"(a0), "r"(a1), "r"(a2), "r"(a3), "r"(b0), "r"(b1));
}
__device__ __forceinline__ void t2ins(float& b1, int& i1, float& b2, int& i2, float s, int c) {
    if (s < b1 || (s == b1 && c < i1)) { b2 = b1; i2 = i1; b1 = s; i1 = c; }
    else if (s < b2 || (s == b2 && c < i2)) { b2 = s; i2 = c; }
}
__device__ __forceinline__ void ins4(float* ts, int* tc, float s, int c) {
    if (s < ts[3]) {
        if (s < ts[1]) {
            ts[3] = ts[2]; tc[3] = tc[2]; ts[2] = ts[1]; tc[2] = tc[1];
            if (s < ts[0]) { ts[1] = ts[0]; tc[1] = tc[0]; ts[0] = s; tc[0] = c; }
            else           { ts[1] = s; tc[1] = c; }
        } else {
            if (s < ts[2]) { ts[3] = ts[2]; tc[3] = tc[2]; ts[2] = s; tc[2] = c; }
            else           { ts[3] = s; tc[3] = c; }
        }
    }
}

// ---------------- kernel 0: normalize codebook + fragment pack ------------------
// 64 blocks x 256 threads; one warp per code. (chains identical to R7-R15)
__global__ void k0_emb(const float* __restrict__ emb0) {
    const int tid = threadIdx.x, w = tid >> 5, tx = tid & 31;
    const int c = blockIdx.x * 8 + w;

    float4 v = *reinterpret_cast<const float4*>(&emb0[c * VDIM + tx * 4]);
    float p0 = __fmul_rn(v.x, v.x), p1 = __fmul_rn(v.y, v.y);
    float p2 = __fmul_rn(v.z, v.z), p3 = __fmul_rn(v.w, v.w);
    float ss = wredsum(__fadd_rn(__fadd_rn(__fadd_rn(p0, p1), p2), p3));
    float nrm = __fsqrt_rn(ss);

    float4 e;
    e.x = __fdiv_rn(__fmul_rn(TNF, v.x), nrm);
    e.y = __fdiv_rn(__fmul_rn(TNF, v.y), nrm);
    e.z = __fdiv_rn(__fmul_rn(TNF, v.z), nrm);
    e.w = __fdiv_rn(__fmul_rn(TNF, v.w), nrm);

    *reinterpret_cast<float4*>(&g_emb[c * VDIM + tx * 4]) = e;

    // fragment pack: k = 4*tx + j ; dst = c*128 + (k&3)*32 + 2*(k>>3) + ((k>>2)&1)
    float ev[4] = {e.x, e.y, e.z, e.w};
    #pragma unroll
    for (int j = 0; j < 4; ++j) {
        int k = tx * 4 + j;
        int dst = c * VDIM + (k & 3) * 32 + 2 * (k >> 3) + ((k >> 2) & 1);
        g_embF[dst] = __uint_as_float(tf32b(ev[j]));
    }

    double e2d = (double)e.x*e.x + (double)e.y*e.y + (double)e.z*e.z + (double)e.w*e.w;
    e2d = wredsumd(e2d);
    if (tx == 0) { g_e2d[c] = e2d; g_e2[c] = (float)e2d; }
}

// ---------------- kernel 2: tf32 mma.sync filter + exact rescore + outputs ------
// R12-best structure (smem-staged B, fragment order) + last-block entropy fusion.
#define MT        128
#define XS_STRIDE 132
#define FR_T      36                                  // padded words per (code,t) row
#define FR_N      (4*FR_T)                            // 144 words per code
#define SM_XS     0                                   // 67584
#define SM_BPK    67584                               // 64*144*4 = 36864
#define SM_E2     104448                              // 2048
#define SM_S2     106496                              // 512
#define SM_IDX    107008                              // 512
#define SM_RC     107520                              // 512
#define SM_FLAG   108032                              // 392
#define SM_WLC    108424                              // 16
#define SM_TOTAL  108544
// aliased into BPK after GEMM chunks complete:
#define SM_CAND   (SM_BPK)                            // 8192
#define SM_CSC    (SM_BPK + 8192)                     // 8192
#define SM_WL     (SM_BPK + 16384)                    // 8192

__global__ void __launch_bounds__(256, 2)
k2_fused(const float* __restrict__ x0, float* __restrict__ out) {
    extern __shared__ char smem[];
    float* xs    = reinterpret_cast<float*>(smem + SM_XS);
    float* bpk   = reinterpret_cast<float*>(smem + SM_BPK);
    float* e2s   = reinterpret_cast<float*>(smem + SM_E2);
    float* s_s2  = reinterpret_cast<float*>(smem + SM_S2);
    int*   s_idx = reinterpret_cast<int*>(smem + SM_IDX);
    int*   s_rc  = reinterpret_cast<int*>(smem + SM_RC);
    int*   s_flag= reinterpret_cast<int*>(smem + SM_FLAG);
    int*   s_wlc = reinterpret_cast<int*>(smem + SM_WLC);
    int*   s_cand= reinterpret_cast<int*>(smem + SM_CAND);
    float* s_csc = reinterpret_cast<float*>(smem + SM_CSC);
    int*   s_wl  = reinterpret_cast<int*>(smem + SM_WL);

    const int tid = threadIdx.x, w = tid >> 5, tx = tid & 31;
    const int g = tx >> 2, t = tx & 3;
    const int rb = blockIdx.x * MT;
    const float FMAX = 3.402823466e38f;

    // ---- x tile: normalize (bit-identical chain), s2 ----
    #pragma unroll
    for (int it = 0; it < 16; ++it) {
        int r = it * 8 + w;
        float4 xv = *reinterpret_cast<const float4*>(&x0[(size_t)(rb + r) * VDIM + tx * 4]);
        float p0 = __fmul_rn(xv.x, xv.x), p1 = __fmul_rn(xv.y, xv.y);
        float p2 = __fmul_rn(xv.z, xv.z), p3 = __fmul_rn(xv.w, xv.w);
        float ss = wredsum(__fadd_rn(__fadd_rn(__fadd_rn(p0, p1), p2), p3));
        float nrm = __fsqrt_rn(ss);
        float4 o;
        o.x = __fdiv_rn(__fmul_rn(TNF, xv.x), nrm);
        o.y = __fdiv_rn(__fmul_rn(TNF, xv.y), nrm);
        o.z = __fdiv_rn(__fmul_rn(TNF, xv.z), nrm);
        o.w = __fdiv_rn(__fmul_rn(TNF, xv.w), nrm);
        *reinterpret_cast<float4*>(&xs[r * XS_STRIDE + tx * 4]) = o;
        float ea = o.x - xv.x, eb = o.y - xv.y, ec = o.z - xv.z, ed = o.w - xv.w;
        float s2 = wredsum(ea*ea + eb*eb + ec*ec + ed*ed);
        if (tx == 0) s_s2[r] = s2;
    }
    e2s[tid] = g_e2[tid];
    e2s[tid + 256] = g_e2[tid + 256];
    __syncthreads();

    // ---- A fragments: warp w owns rows w*16 .. w*16+15; tf32 in regs ----
    uint32_t afr[16][4];
    {
        const float* xw = xs + (w * 16) * XS_STRIDE;
        #pragma unroll
        for (int ks = 0; ks < 16; ++ks) {
            afr[ks][0] = tf32b(xw[ g      * XS_STRIDE + ks * 8 + t    ]);
            afr[ks][1] = tf32b(xw[(g + 8) * XS_STRIDE + ks * 8 + t    ]);
            afr[ks][2] = tf32b(xw[ g      * XS_STRIDE + ks * 8 + t + 4]);
            afr[ks][3] = tf32b(xw[(g + 8) * XS_STRIDE + ks * 8 + t + 4]);
        }
    }

    float tsA[4] = {FMAX, FMAX, FMAX, FMAX}, tsB[4] = {FMAX, FMAX, FMAX, FMAX};
    int   tcA[4] = {0, 0, 0, 0},             tcB[4] = {0, 0, 0, 0};

    for (int chunk = 0; chunk < 8; ++chunk) {
        __syncthreads();
        // stage B chunk in fragment order: bpk[n*FR_N + t*FR_T + j], j=0..31
        #pragma unroll
        for (int it = 0; it < 8; ++it) {
            int i   = tid + it * 256;        // over (n 0..63, t 0..3, j4 0..7)
            int n   = i >> 5;
            int rem = i & 31;
            int tt  = rem >> 3;
            int j4  = rem & 7;
            float4 v = *reinterpret_cast<const float4*>(
                &g_embF[(chunk * 64 + n) * VDIM + tt * 32 + j4 * 4]);
            *reinterpret_cast<float4*>(&bpk[n * FR_N + tt * FR_T + j4 * 4]) = v;
        }
        __syncthreads();

        #pragma unroll
        for (int nt = 0; nt < 8; ++nt) {
            float d0 = 0.f, d1 = 0.f, d2 = 0.f, d3 = 0.f;
            const float* bp = &bpk[(nt * 8 + g) * FR_N + t * FR_T];
            #pragma unroll
            for (int ks2 = 0; ks2 < 8; ++ks2) {
                float4 bq = *reinterpret_cast<const float4*>(bp + ks2 * 4);
                int ks = ks2 * 2;
                mma_tf32(d0, d1, d2, d3,
                         afr[ks][0], afr[ks][1], afr[ks][2], afr[ks][3],
                         __float_as_uint(bq.x), __float_as_uint(bq.y));
                mma_tf32(d0, d1, d2, d3,
                         afr[ks+1][0], afr[ks+1][1], afr[ks+1][2], afr[ks+1][3],
                         __float_as_uint(bq.z), __float_as_uint(bq.w));
            }
            int c0 = chunk * 64 + nt * 8 + t * 2;
            float2 e2v = *reinterpret_cast<const float2*>(&e2s[c0]);
            float sA0 = __fsub_rn(e2v.x, __fmul_rn(2.0f, d0));
            float sA1 = __fsub_rn(e2v.y, __fmul_rn(2.0f, d1));
            float sB0 = __fsub_rn(e2v.x, __fmul_rn(2.0f, d2));
            float sB1 = __fsub_rn(e2v.y, __fmul_rn(2.0f, d3));
            ins4(tsA, tcA, sA0, c0); ins4(tsA, tcA, sA1, c0 + 1);
            ins4(tsB, tcB, sB0, c0); ins4(tsB, tcB, sB1, c0 + 1);
        }
    }
    __syncthreads();

    // ---- init candidate structures (BPK now free to alias) ----
    if (tid < MT) s_rc[tid] = 0;
    if (tid == 0) { s_flag[0] = 0; s_wlc[0] = 0; }
    __syncthreads();

    // ---- per-row candidate collection (group-of-4 lanes per row) ----
    {
        #pragma unroll
        for (int h = 0; h < 2; ++h) {
            float* ts = h ? tsB : tsA;
            int*   tc = h ? tcB : tcA;
            int row = w * 16 + g + h * 8;
            float gb = ts[0];
            gb = fminf(gb, __shfl_xor_sync(0xffffffffu, gb, 1));
            gb = fminf(gb, __shfl_xor_sync(0xffffffffu, gb, 2));
            float th = __fadd_rn(gb, BAND);
            int ov = (ts[3] <= th) ? 1 : 0;
            ov |= __shfl_xor_sync(0xffffffffu, ov, 1);
            ov |= __shfl_xor_sync(0xffffffffu, ov, 2);
            if (ov) {
                if (t == 0) s_rc[row] = -1;          // fallback sentinel
            } else {
                #pragma unroll
                for (int i = 0; i < 4; ++i) {
                    if (ts[i] <= th) {
                        int pos = atomicAdd(&s_rc[row], 1);
                        s_cand[row * 16 + pos] = tc[i];
                    }
                }
            }
        }
    }
    __syncthreads();

    // ---- worklist ----
    if (tid < MT) {
        int rc = s_rc[tid];
        for (int s = 0; s < rc; ++s) {
            int pos = atomicAdd(s_wlc, 1);
            s_wl[pos] = tid * 16 + s;
        }
    }
    __syncthreads();

    // ---- exact fp32-chain rescore (bitwise identical chain to R7-R15) ----
    int wlc = s_wlc[0];
    for (int p = tid; p < wlc; p += 256) {
        int ent = s_wl[p];
        int r = ent >> 4, slot = ent & 15;
        int code = s_cand[ent];
        const float* xr = xs + r * XS_STRIDE;
        const float* er = g_emb + code * VDIM;
        float acc = 0.0f;
        #pragma unroll 8
        for (int k4 = 0; k4 < 32; ++k4) {
            float4 xv = *reinterpret_cast<const float4*>(xr + k4 * 4);
            float4 ev = *reinterpret_cast<const float4*>(er + k4 * 4);
            acc = __fmaf_rn(xv.x, ev.x, acc);
            acc = __fmaf_rn(xv.y, ev.y, acc);
            acc = __fmaf_rn(xv.z, ev.z, acc);
            acc = __fmaf_rn(xv.w, ev.w, acc);
        }
        s_csc[r * 16 + slot] = __fsub_rn(e2s[code], __fmul_rn(2.0f, acc));
    }
    __syncthreads();

    // ---- per-row top-2 over exact scores + gap flag ----
    if (tid < MT && s_rc[tid] > 0) {
        int rc = s_rc[tid];
        float b1 = FMAX, b2 = FMAX;
        int i1 = 0x3fffffff, i2 = 0x3fffffff;
        for (int s = 0; s < rc; ++s)
            t2ins(b1, i1, b2, i2, s_csc[tid * 16 + s], s_cand[tid * 16 + s]);
        s_idx[tid] = i1;
        if (__fsub_rn(b2, b1) < GAP_THR) {
            int e = atomicAdd(&s_flag[0], 1);
            if (e < FLAGCAP) {
                s_flag[1 + 3*e + 0] = tid;
                s_flag[1 + 3*e + 1] = i1;
                s_flag[1 + 3*e + 2] = i2;
            }
        }
    }
    __syncthreads();

    // ---- fallback rows: exact full-scan, warp per row ----
    for (int r = w; r < MT; r += 8) {
        if (s_rc[r] >= 0) continue;
        const float* xr = xs + r * XS_STRIDE;
        float b1 = FMAX, b2 = FMAX;
        int i1 = 0x3fffffff, i2 = 0x3fffffff;
        for (int j = 0; j < 16; ++j) {
            int code = j * 32 + tx;
            const float* er = g_emb + code * VDIM;
            float acc = 0.0f;
            #pragma unroll 8
            for (int k4 = 0; k4 < 32; ++k4) {
                float4 xv = *reinterpret_cast<const float4*>(xr + k4 * 4);
                float4 ev = *reinterpret_cast<const float4*>(er + k4 * 4);
                acc = __fmaf_rn(xv.x, ev.x, acc);
                acc = __fmaf_rn(xv.y, ev.y, acc);
                acc = __fmaf_rn(xv.z, ev.z, acc);
                acc = __fmaf_rn(xv.w, ev.w, acc);
            }
            t2ins(b1, i1, b2, i2, __fsub_rn(e2s[code], __fmul_rn(2.0f, acc)), code);
        }
        #pragma unroll
        for (int off = 16; off > 0; off >>= 1) {
            float ob1 = __shfl_xor_sync(0xffffffffu, b1, off);
            int   oi1 = __shfl_xor_sync(0xffffffffu, i1, off);
            float ob2 = __shfl_xor_sync(0xffffffffu, b2, off);
            int   oi2 = __shfl_xor_sync(0xffffffffu, i2, off);
            t2ins(b1, i1, b2, i2, ob1, oi1);
            t2ins(b1, i1, b2, i2, ob2, oi2);
        }
        if (tx == 0) {
            s_idx[r] = i1;
            if (__fsub_rn(b2, b1) < GAP_THR) {
                int e = atomicAdd(&s_flag[0], 1);
                if (e < FLAGCAP) {
                    s_flag[1 + 3*e + 0] = r;
                    s_flag[1 + 3*e + 1] = i1;
                    s_flag[1 + 3*e + 2] = i2;
                }
            }
        }
    }
    __syncthreads();

    // ---- fp64 margin refine (warp 0; bit-identical to R7-R15 path) ----
    if (w == 0) {
        int cnt = s_flag[0]; if (cnt > FLAGCAP) cnt = FLAGCAP;
        for (int e = 0; e < cnt; ++e) {
            int r  = s_flag[1 + 3*e + 0];
            int i1 = s_flag[1 + 3*e + 1];
            int i2 = s_flag[1 + 3*e + 2];
            float4 xn = *reinterpret_cast<const float4*>(&xs[r * XS_STRIDE + tx * 4]);
            float4 e1 = *reinterpret_cast<const float4*>(&g_emb[i1 * VDIM + tx * 4]);
            float4 e2 = *reinterpret_cast<const float4*>(&g_emb[i2 * VDIM + tx * 4]);
            double d1 = (double)xn.x*e1.x + (double)xn.y*e1.y + (double)xn.z*e1.z + (double)xn.w*e1.w;
            double d2 = (double)xn.x*e2.x + (double)xn.y*e2.y + (double)xn.z*e2.z + (double)xn.w*e2.w;
            d1 = wredsumd(d1); d2 = wredsumd(d2);
            double s1d = g_e2d[i1] - 2.0 * d1;
            double s2d = g_e2d[i2] - 2.0 * d2;
            bool w2 = (s2d < s1d) || (s2d == s1d && i2 < i1);
            double margin = w2 ? (s1d - s2d) : (s2d - s1d);
            bool take2 = w2 ^ (margin < TIE_EPS);
            if (tx == 0 && take2) s_idx[r] = i2;
        }
    }
    __syncthreads();

    // ---- outputs ----
    #pragma unroll
    for (int it = 0; it < 16; ++it) {
        int r   = it * 8 + w;
        int idx = s_idx[r];
        float4 xn = *reinterpret_cast<const float4*>(&xs[r * XS_STRIDE + tx * 4]);
        float4 ev = *reinterpret_cast<const float4*>(&g_emb[idx * VDIM + tx * 4]);
        float4 o0;
        o0.x = __fadd_rn(__fsub_rn(ev.x, xn.x), xn.x);
        o0.y = __fadd_rn(__fsub_rn(ev.y, xn.y), xn.y);
        o0.z = __fadd_rn(__fsub_rn(ev.z, xn.z), xn.z);
        o0.w = __fadd_rn(__fsub_rn(ev.w, xn.w), xn.w);
        *reinterpret_cast<float4*>(&out[(size_t)(rb + r) * VDIM + tx * 4]) = o0;

        float da = xn.x - ev.x, db = xn.y - ev.y, dc = xn.z - ev.z, dd = xn.w - ev.w;
        float s1 = wredsum(da*da + db*db + dc*dc + dd*dd);
        if (tx == 0) {
            out[O1_OFF + rb + r] = s1;
            out[O2_OFF + rb + r] = __fadd_rn(s1, s_s2[r]);
            atomicAdd(&g_hist[idx], 1);
        }
    }

    // ---- last block: entropy + hist/counter reset (validated in R15) ----
    __syncthreads();
    if (tid == 0) {
        __threadfence();
        int v = atomicAdd(&g_done, 1);
        s_wlc[1] = (v == (int)gridDim.x - 1) ? 1 : 0;
    }
    __syncthreads();
    if (s_wlc[1]) {
        __threadfence();
        int h0 = g_hist[tid], h1 = g_hist[tid + 256];
        float pa = (float)h0 * (1.0f / 131072.0f);
        float pb = (float)h1 * (1.0f / 131072.0f);
        float term = ((h0 > 0) ? (-pa * logf(pa)) : 0.0f)
                   + ((h1 > 0) ? (-pb * logf(pb)) : 0.0f);
        term = wredsum(term);
        __shared__ float ws[8];
        if (tx == 0) ws[w] = term;
        __syncthreads();
        if (tid < 32) {
            float vsum = (tid < 8) ? ws[tid] : 0.0f;
            #pragma unroll
            for (int o = 4; o > 0; o >>= 1) vsum += __shfl_xor_sync(0xffffffffu, vsum, o);
            if (tid == 0) { out[OE_OFF] = vsum; g_done = 0; }
        }
        g_hist[tid] = 0; g_hist[tid + 256] = 0;
    }
}

// ---------------- launch --------------------------------------------------------
extern "C" void kernel_launch(void* const* d_in, const int* in_sizes, int n_in,
                              void* d_out, int out_size) {
    const float* x0   = (const float*)d_in[0];
    const float* emb0 = (const float*)d_in[1];
    if (n_in >= 2 && in_sizes[0] == KCODES * VDIM) {
        x0   = (const float*)d_in[1];
        emb0 = (const float*)d_in[0];
    }
    float* out = (float*)d_out;

    cudaFuncSetAttribute(k2_fused,
                         cudaFuncAttributeMaxDynamicSharedMemorySize, SM_TOTAL);

    k0_emb<<<64, 256>>>(emb0);
    k2_fused<<<NROWS / MT, 256, SM_TOTAL>>>(x0, out);
}

// round 17
// speedup vs baseline: 2.4887x; 1.0673x over previous
#include <cuda_runtime.h>
#include <cstdint>

// Problem constants
#define NROWS   131072
#define VDIM    128
#define KCODES  512
#define TNF     0.678822509939086f   // fl32(0.06 * sqrt(128))

#define TIE_EPS 4e-7                 // fp64 near-tie margin (R7+ passing rule)
#define GAP_THR 1e-4f                // fp32 gap below which fp64 refine runs
#define BAND    2.5e-3f              // tf32 candidate band >= GAP_THR + 4*tf32 dot err
#define FLAGCAP 32

#define O1_OFF  (131072*128)
#define O2_OFF  (O1_OFF + 131072)
#define OE_OFF  (O2_OFF + 131072)

// ---------------- scratch ------------------------------------------------------
__device__ float  g_emb[KCODES*VDIM];     // normalized codebook fp32, code-major
__device__ float  g_embF[KCODES*VDIM];    // tf32 codebook in MMA fragment order
__device__ float  g_e2[KCODES];
__device__ double g_e2d[KCODES];
__device__ int    g_hist[KCODES];

// ---------------- helpers ------------------------------------------------------
__device__ __forceinline__ float wredsum(float v) {
    #pragma unroll
    for (int o = 16; o > 0; o >>= 1) v += __shfl_xor_sync(0xffffffffu, v, o);
    return v;
}
__device__ __forceinline__ double wredsumd(double v) {
    #pragma unroll
    for (int o = 16; o > 0; o >>= 1) v += __shfl_xor_sync(0xffffffffu, v, o);
    return v;
}
__device__ __forceinline__ uint32_t tf32b(float x) {
    unsigned r;
    asm("cvt.rna.tf32.f32 %0, %1;" : "=r"(r) : "f"(x));
    return r;
}
__device__ __forceinline__ void mma_tf32(float& d0, float& d1, float& d2, float& d3,
                                         uint32_t a0, uint32_t a1, uint32_t a2, uint32_t a3,
                                         uint32_t b0, uint32_t b1) {
    asm volatile("mma.sync.aligned.m16n8k8.row.col.f32.tf32.tf32.f32 "
                 "{%0,%1,%2,%3}, {%4,%5,%6,%7}, {%8,%9}, {%0,%1,%2,%3};"
                 : "+f"(d0), "+f"(d1), "+f"(d2), "+f"(d3)
                 : "r"(a0), "r"(a1), "r"(a2), "r"(a3), "r"(b0), "r"(b1));
}
__device__ __forceinline__ void t2ins(float& b1, int& i1, float& b2, int& i2, float s, int c) {
    if (s < b1 || (s == b1 && c < i1)) { b2 = b1; i2 = i1; b1 = s; i1 = c; }
    else if (s < b2 || (s == b2 && c < i2)) { b2 = s; i2 = c; }
}
__device__ __forceinline__ void ins4(float* ts, int* tc, float s, int c) {
    if (s < ts[3]) {
        if (s < ts[1]) {
            ts[3] = ts[2]; tc[3] = tc[2]; ts[2] = ts[1]; tc[2] = tc[1];
            if (s < ts[0]) { ts[1] = ts[0]; tc[1] = tc[0]; ts[0] = s; tc[0] = c; }
            else           { ts[1] = s; tc[1] = c; }
        } else {
            if (s < ts[2]) { ts[3] = ts[2]; tc[3] = tc[2]; ts[2] = s; tc[2] = c; }
            else           { ts[3] = s; tc[3] = c; }
        }
    }
}

// ---- cold paths, NOT inlined: keep fp64/fallback register classes out of the
// hot kernel allocation. Warp-uniform call sites (whole warp enters together).
__device__ __noinline__ void fallback_row(const float* xr, const float* e2s,
                                          int r, int tx,
                                          int* s_idx, int* s_flag) {
    const float FMAX = 3.402823466e38f;
    float b1 = FMAX, b2 = FMAX;
    int i1 = 0x3fffffff, i2 = 0x3fffffff;
    for (int j = 0; j < 16; ++j) {
        int code = j * 32 + tx;
        const float* er = g_emb + code * VDIM;
        float acc = 0.0f;
        #pragma unroll 8
        for (int k4 = 0; k4 < 32; ++k4) {
            float4 xv = *reinterpret_cast<const float4*>(xr + k4 * 4);
            float4 ev = *reinterpret_cast<const float4*>(er + k4 * 4);
            acc = __fmaf_rn(xv.x, ev.x, acc);
            acc = __fmaf_rn(xv.y, ev.y, acc);
            acc = __fmaf_rn(xv.z, ev.z, acc);
            acc = __fmaf_rn(xv.w, ev.w, acc);
        }
        t2ins(b1, i1, b2, i2, __fsub_rn(e2s[code], __fmul_rn(2.0f, acc)), code);
    }
    #pragma unroll
    for (int off = 16; off > 0; off >>= 1) {
        float ob1 = __shfl_xor_sync(0xffffffffu, b1, off);
        int   oi1 = __shfl_xor_sync(0xffffffffu, i1, off);
        float ob2 = __shfl_xor_sync(0xffffffffu, b2, off);
        int   oi2 = __shfl_xor_sync(0xffffffffu, i2, off);
        t2ins(b1, i1, b2, i2, ob1, oi1);
        t2ins(b1, i1, b2, i2, ob2, oi2);
    }
    if (tx == 0) {
        s_idx[r] = i1;
        if (__fsub_rn(b2, b1) < GAP_THR) {
            int e = atomicAdd(&s_flag[0], 1);
            if (e < FLAGCAP) {
                s_flag[1 + 3*e + 0] = r;
                s_flag[1 + 3*e + 1] = i1;
                s_flag[1 + 3*e + 2] = i2;
            }
        }
    }
}

__device__ __noinline__ void refine_flags(const float* xs, int xs_stride, int tx,
                                          int* s_idx, const int* s_flag) {
    int cnt = s_flag[0]; if (cnt > FLAGCAP) cnt = FLAGCAP;
    for (int e = 0; e < cnt; ++e) {
        int r  = s_flag[1 + 3*e + 0];
        int i1 = s_flag[1 + 3*e + 1];
        int i2 = s_flag[1 + 3*e + 2];
        float4 xn = *reinterpret_cast<const float4*>(&xs[r * xs_stride + tx * 4]);
        float4 e1 = *reinterpret_cast<const float4*>(&g_emb[i1 * VDIM + tx * 4]);
        float4 e2 = *reinterpret_cast<const float4*>(&g_emb[i2 * VDIM + tx * 4]);
        double d1 = (double)xn.x*e1.x + (double)xn.y*e1.y + (double)xn.z*e1.z + (double)xn.w*e1.w;
        double d2 = (double)xn.x*e2.x + (double)xn.y*e2.y + (double)xn.z*e2.z + (double)xn.w*e2.w;
        d1 = wredsumd(d1); d2 = wredsumd(d2);
        double s1d = g_e2d[i1] - 2.0 * d1;
        double s2d = g_e2d[i2] - 2.0 * d2;
        bool w2 = (s2d < s1d) || (s2d == s1d && i2 < i1);
        double margin = w2 ? (s1d - s2d) : (s2d - s1d);
        bool take2 = w2 ^ (margin < TIE_EPS);
        if (tx == 0 && take2) s_idx[r] = i2;
    }
}

// ---------------- kernel 0: normalize codebook + fragment pack ------------------
__global__ void k0_emb(const float* __restrict__ emb0) {
    const int tid = threadIdx.x, w = tid >> 5, tx = tid & 31;
    const int c = blockIdx.x * 8 + w;
    if (blockIdx.x == 0 && tid < 256) { g_hist[tid] = 0; g_hist[tid + 256] = 0; }

    float4 v = *reinterpret_cast<const float4*>(&emb0[c * VDIM + tx * 4]);
    float p0 = __fmul_rn(v.x, v.x), p1 = __fmul_rn(v.y, v.y);
    float p2 = __fmul_rn(v.z, v.z), p3 = __fmul_rn(v.w, v.w);
    float ss = wredsum(__fadd_rn(__fadd_rn(__fadd_rn(p0, p1), p2), p3));
    float nrm = __fsqrt_rn(ss);

    float4 e;
    e.x = __fdiv_rn(__fmul_rn(TNF, v.x), nrm);
    e.y = __fdiv_rn(__fmul_rn(TNF, v.y), nrm);
    e.z = __fdiv_rn(__fmul_rn(TNF, v.z), nrm);
    e.w = __fdiv_rn(__fmul_rn(TNF, v.w), nrm);

    *reinterpret_cast<float4*>(&g_emb[c * VDIM + tx * 4]) = e;

    // fragment pack: k = 4*tx + j ; dst = c*128 + (k&3)*32 + 2*(k>>3) + ((k>>2)&1)
    float ev[4] = {e.x, e.y, e.z, e.w};
    #pragma unroll
    for (int j = 0; j < 4; ++j) {
        int k = tx * 4 + j;
        int dst = c * VDIM + (k & 3) * 32 + 2 * (k >> 3) + ((k >> 2) & 1);
        g_embF[dst] = __uint_as_float(tf32b(ev[j]));
    }

    double e2d = (double)e.x*e.x + (double)e.y*e.y + (double)e.z*e.z + (double)e.w*e.w;
    e2d = wredsumd(e2d);
    if (tx == 0) { g_e2d[c] = e2d; g_e2[c] = (float)e2d; }
}

// ---------------- kernel 2: tf32 mma.sync filter + exact rescore + outputs ------
// Exact R12-best structure (smem-staged B in fragment order).
#define MT        128
#define XS_STRIDE 132
#define FR_T      36
#define FR_N      (4*FR_T)
#define SM_XS     0                                   // 67584
#define SM_BPK    67584                               // 36864
#define SM_E2     104448                              // 2048
#define SM_S2     106496                              // 512
#define SM_IDX    107008                              // 512
#define SM_RC     107520                              // 512
#define SM_FLAG   108032                              // 392
#define SM_WLC    108424                               // 4
#define SM_TOTAL  108544
#define SM_CAND   (SM_BPK)                            // 8192 (aliased after GEMM)
#define SM_CSC    (SM_BPK + 8192)                     // 8192
#define SM_WL     (SM_BPK + 16384)                    // 8192

__global__ void __launch_bounds__(256, 2)
k2_fused(const float* __restrict__ x0, float* __restrict__ out) {
    extern __shared__ char smem[];
    float* xs    = reinterpret_cast<float*>(smem + SM_XS);
    float* bpk   = reinterpret_cast<float*>(smem + SM_BPK);
    float* e2s   = reinterpret_cast<float*>(smem + SM_E2);
    float* s_s2  = reinterpret_cast<float*>(smem + SM_S2);
    int*   s_idx = reinterpret_cast<int*>(smem + SM_IDX);
    int*   s_rc  = reinterpret_cast<int*>(smem + SM_RC);
    int*   s_flag= reinterpret_cast<int*>(smem + SM_FLAG);
    int*   s_wlc = reinterpret_cast<int*>(smem + SM_WLC);
    int*   s_cand= reinterpret_cast<int*>(smem + SM_CAND);
    float* s_csc = reinterpret_cast<float*>(smem + SM_CSC);
    int*   s_wl  = reinterpret_cast<int*>(smem + SM_WL);

    const int tid = threadIdx.x, w = tid >> 5, tx = tid & 31;
    const int g = tx >> 2, t = tx & 3;
    const int rb = blockIdx.x * MT;
    const float FMAX = 3.402823466e38f;

    // ---- x tile: normalize (bit-identical chain), s2 ----
    #pragma unroll
    for (int it = 0; it < 16; ++it) {
        int r = it * 8 + w;
        float4 xv = *reinterpret_cast<const float4*>(&x0[(size_t)(rb + r) * VDIM + tx * 4]);
        float p0 = __fmul_rn(xv.x, xv.x), p1 = __fmul_rn(xv.y, xv.y);
        float p2 = __fmul_rn(xv.z, xv.z), p3 = __fmul_rn(xv.w, xv.w);
        float ss = wredsum(__fadd_rn(__fadd_rn(__fadd_rn(p0, p1), p2), p3));
        float nrm = __fsqrt_rn(ss);
        float4 o;
        o.x = __fdiv_rn(__fmul_rn(TNF, xv.x), nrm);
        o.y = __fdiv_rn(__fmul_rn(TNF, xv.y), nrm);
        o.z = __fdiv_rn(__fmul_rn(TNF, xv.z), nrm);
        o.w = __fdiv_rn(__fmul_rn(TNF, xv.w), nrm);
        *reinterpret_cast<float4*>(&xs[r * XS_STRIDE + tx * 4]) = o;
        float ea = o.x - xv.x, eb = o.y - xv.y, ec = o.z - xv.z, ed = o.w - xv.w;
        float s2 = wredsum(ea*ea + eb*eb + ec*ec + ed*ed);
        if (tx == 0) s_s2[r] = s2;
    }
    e2s[tid] = g_e2[tid];
    e2s[tid + 256] = g_e2[tid + 256];
    __syncthreads();

    // ---- A fragments: warp w owns rows w*16 .. w*16+15; tf32 in regs ----
    uint32_t afr[16][4];
    {
        const float* xw = xs + (w * 16) * XS_STRIDE;
        #pragma unroll
        for (int ks = 0; ks < 16; ++ks) {
            afr[ks][0] = tf32b(xw[ g      * XS_STRIDE + ks * 8 + t    ]);
            afr[ks][1] = tf32b(xw[(g + 8) * XS_STRIDE + ks * 8 + t    ]);
            afr[ks][2] = tf32b(xw[ g      * XS_STRIDE + ks * 8 + t + 4]);
            afr[ks][3] = tf32b(xw[(g + 8) * XS_STRIDE + ks * 8 + t + 4]);
        }
    }

    float tsA[4] = {FMAX, FMAX, FMAX, FMAX}, tsB[4] = {FMAX, FMAX, FMAX, FMAX};
    int   tcA[4] = {0, 0, 0, 0},             tcB[4] = {0, 0, 0, 0};

    for (int chunk = 0; chunk < 8; ++chunk) {
        __syncthreads();
        #pragma unroll
        for (int it = 0; it < 8; ++it) {
            int i   = tid + it * 256;
            int n   = i >> 5;
            int rem = i & 31;
            int tt  = rem >> 3;
            int j4  = rem & 7;
            float4 v = *reinterpret_cast<const float4*>(
                &g_embF[(chunk * 64 + n) * VDIM + tt * 32 + j4 * 4]);
            *reinterpret_cast<float4*>(&bpk[n * FR_N + tt * FR_T + j4 * 4]) = v;
        }
        __syncthreads();

        #pragma unroll
        for (int nt = 0; nt < 8; ++nt) {
            float d0 = 0.f, d1 = 0.f, d2 = 0.f, d3 = 0.f;
            const float* bp = &bpk[(nt * 8 + g) * FR_N + t * FR_T];
            #pragma unroll
            for (int ks2 = 0; ks2 < 8; ++ks2) {
                float4 bq = *reinterpret_cast<const float4*>(bp + ks2 * 4);
                int ks = ks2 * 2;
                mma_tf32(d0, d1, d2, d3,
                         afr[ks][0], afr[ks][1], afr[ks][2], afr[ks][3],
                         __float_as_uint(bq.x), __float_as_uint(bq.y));
                mma_tf32(d0, d1, d2, d3,
                         afr[ks+1][0], afr[ks+1][1], afr[ks+1][2], afr[ks+1][3],
                         __float_as_uint(bq.z), __float_as_uint(bq.w));
            }
            int c0 = chunk * 64 + nt * 8 + t * 2;
            float2 e2v = *reinterpret_cast<const float2*>(&e2s[c0]);
            float sA0 = __fsub_rn(e2v.x, __fmul_rn(2.0f, d0));
            float sA1 = __fsub_rn(e2v.y, __fmul_rn(2.0f, d1));
            float sB0 = __fsub_rn(e2v.x, __fmul_rn(2.0f, d2));
            float sB1 = __fsub_rn(e2v.y, __fmul_rn(2.0f, d3));
            ins4(tsA, tcA, sA0, c0); ins4(tsA, tcA, sA1, c0 + 1);
            ins4(tsB, tcB, sB0, c0); ins4(tsB, tcB, sB1, c0 + 1);
        }
    }
    __syncthreads();

    // ---- init candidate structures (BPK now free to alias) ----
    if (tid < MT) s_rc[tid] = 0;
    if (tid == 0) { s_flag[0] = 0; s_wlc[0] = 0; }
    __syncthreads();

    // ---- per-row candidate collection (group-of-4 lanes per row) ----
    {
        #pragma unroll
        for (int h = 0; h < 2; ++h) {
            float* ts = h ? tsB : tsA;
            int*   tc = h ? tcB : tcA;
            int row = w * 16 + g + h * 8;
            float gb = ts[0];
            gb = fminf(gb, __shfl_xor_sync(0xffffffffu, gb, 1));
            gb = fminf(gb, __shfl_xor_sync(0xffffffffu, gb, 2));
            float th = __fadd_rn(gb, BAND);
            int ov = (ts[3] <= th) ? 1 : 0;
            ov |= __shfl_xor_sync(0xffffffffu, ov, 1);
            ov |= __shfl_xor_sync(0xffffffffu, ov, 2);
            if (ov) {
                if (t == 0) s_rc[row] = -1;
            } else {
                #pragma unroll
                for (int i = 0; i < 4; ++i) {
                    if (ts[i] <= th) {
                        int pos = atomicAdd(&s_rc[row], 1);
                        s_cand[row * 16 + pos] = tc[i];
                    }
                }
            }
        }
    }
    __syncthreads();

    // ---- worklist ----
    if (tid < MT) {
        int rc = s_rc[tid];
        for (int s = 0; s < rc; ++s) {
            int pos = atomicAdd(s_wlc, 1);
            s_wl[pos] = tid * 16 + s;
        }
    }
    __syncthreads();

    // ---- exact fp32-chain rescore ----
    int wlc = s_wlc[0];
    for (int p = tid; p < wlc; p += 256) {
        int ent = s_wl[p];
        int r = ent >> 4, slot = ent & 15;
        int code = s_cand[ent];
        const float* xr = xs + r * XS_STRIDE;
        const float* er = g_emb + code * VDIM;
        float acc = 0.0f;
        #pragma unroll 8
        for (int k4 = 0; k4 < 32; ++k4) {
            float4 xv = *reinterpret_cast<const float4*>(xr + k4 * 4);
            float4 ev = *reinterpret_cast<const float4*>(er + k4 * 4);
            acc = __fmaf_rn(xv.x, ev.x, acc);
            acc = __fmaf_rn(xv.y, ev.y, acc);
            acc = __fmaf_rn(xv.z, ev.z, acc);
            acc = __fmaf_rn(xv.w, ev.w, acc);
        }
        s_csc[r * 16 + slot] = __fsub_rn(e2s[code], __fmul_rn(2.0f, acc));
    }
    __syncthreads();

    // ---- per-row top-2 over exact scores + gap flag ----
    if (tid < MT && s_rc[tid] > 0) {
        int rc = s_rc[tid];
        float b1 = FMAX, b2 = FMAX;
        int i1 = 0x3fffffff, i2 = 0x3fffffff;
        for (int s = 0; s < rc; ++s)
            t2ins(b1, i1, b2, i2, s_csc[tid * 16 + s], s_cand[tid * 16 + s]);
        s_idx[tid] = i1;
        if (__fsub_rn(b2, b1) < GAP_THR) {
            int e = atomicAdd(&s_flag[0], 1);
            if (e < FLAGCAP) {
                s_flag[1 + 3*e + 0] = tid;
                s_flag[1 + 3*e + 1] = i1;
                s_flag[1 + 3*e + 2] = i2;
            }
        }
    }
    __syncthreads();

    // ---- fallback rows: exact full-scan (cold, noinline) ----
    for (int r = w; r < MT; r += 8) {
        if (s_rc[r] >= 0) continue;
        fallback_row(xs + r * XS_STRIDE, e2s, r, tx, s_idx, s_flag);
    }
    __syncthreads();

    // ---- fp64 margin refine (warp 0; cold, noinline) ----
    if (w == 0) refine_flags(xs, XS_STRIDE, tx, s_idx, s_flag);
    __syncthreads();

    // ---- outputs ----
    #pragma unroll
    for (int it = 0; it < 16; ++it) {
        int r   = it * 8 + w;
        int idx = s_idx[r];
        float4 xn = *reinterpret_cast<const float4*>(&xs[r * XS_STRIDE + tx * 4]);
        float4 ev = *reinterpret_cast<const float4*>(&g_emb[idx * VDIM + tx * 4]);
        float4 o0;
        o0.x = __fadd_rn(__fsub_rn(ev.x, xn.x), xn.x);
        o0.y = __fadd_rn(__fsub_rn(ev.y, xn.y), xn.y);
        o0.z = __fadd_rn(__fsub_rn(ev.z, xn.z), xn.z);
        o0.w = __fadd_rn(__fsub_rn(ev.w, xn.w), xn.w);
        *reinterpret_cast<float4*>(&out[(size_t)(rb + r) * VDIM + tx * 4]) = o0;

        float da = xn.x - ev.x, db = xn.y - ev.y, dc = xn.z - ev.z, dd = xn.w - ev.w;
        float s1 = wredsum(da*da + db*db + dc*dc + dd*dd);
        if (tx == 0) {
            out[O1_OFF + rb + r] = s1;
            out[O2_OFF + rb + r] = __fadd_rn(s1, s_s2[r]);
            atomicAdd(&g_hist[idx], 1);
        }
    }
}

// ---------------- kernel 4: entropy ---------------------------------------------
__global__ void k4_entropy(float* __restrict__ out) {
    const int t = threadIdx.x;   // 512
    int   h = g_hist[t];
    float p = (float)h * (1.0f / 131072.0f);
    float term = (h > 0) ? (-p * logf(p)) : 0.0f;
    term = wredsum(term);
    __shared__ float ws[16];
    if ((t & 31) == 0) ws[t >> 5] = term;
    __syncthreads();
    if (t < 32) {
        float v = (t < 16) ? ws[t] : 0.0f;
        #pragma unroll
        for (int o = 16; o > 0; o >>= 1) v += __shfl_xor_sync(0xffffffffu, v, o);
        if (t == 0) out[OE_OFF] = v;
    }
}

// ---------------- launch --------------------------------------------------------
extern "C" void kernel_launch(void* const* d_in, const int* in_sizes, int n_in,
                              void* d_out, int out_size) {
    const float* x0   = (const float*)d_in[0];
    const float* emb0 = (const float*)d_in[1];
    if (n_in >= 2 && in_sizes[0] == KCODES * VDIM) {
        x0   = (const float*)d_in[1];
        emb0 = (const float*)d_in[0];
    }
    float* out = (float*)d_out;

    cudaFuncSetAttribute(k2_fused,
                         cudaFuncAttributeMaxDynamicSharedMemorySize, SM_TOTAL);

    k0_emb<<<64, 256>>>(emb0);
    k2_fused<<<NROWS / MT, 256, SM_TOTAL>>>(x0, out);
    k4_entropy<<<1, 512>>>(out);
}